// round 14
// baseline (speedup 1.0000x reference)
#include <cuda_runtime.h>
#include <cstdint>
#include <math.h>

// ---------------- problem constants ----------------
#define B_   4
#define S_   2048
#define H_   1024
#define NH_  16
#define HD_  64
#define FF_  4096
#define MR_  (B_*S_)        // 8192 rows

// ---------------- scratch (device globals; no runtime allocation) ----------------
__device__ float g_q  [(size_t)MR_*H_];
__device__ float g_k  [(size_t)MR_*H_];
__device__ float g_v  [(size_t)MR_*H_];
__device__ float g_ctx[(size_t)MR_*H_];
__device__ float g_tmp[(size_t)MR_*H_];
__device__ float g_x1 [(size_t)MR_*H_];
__device__ float g_ff [(size_t)MR_*FF_];

// ---------------- helpers ----------------
__device__ __forceinline__ void cpa16(void* dst, const void* src) {
    uint32_t d = (uint32_t)__cvta_generic_to_shared(dst);
    asm volatile("cp.async.cg.shared.global [%0], [%1], 16;" :: "r"(d), "l"(src));
}
__device__ __forceinline__ void cp_commit() { asm volatile("cp.async.commit_group;"); }
__device__ __forceinline__ void cp_wait0()  { asm volatile("cp.async.wait_group 0;"); }
__device__ __forceinline__ void cp_wait1()  { asm volatile("cp.async.wait_group 1;"); }

// round-to-nearest tf32 (kills the RZ truncation bias; fma-pipe, hidden under mma)
__device__ __forceinline__ float rna(float f) {
    uint32_t u;
    asm("cvt.rna.tf32.f32 %0, %1;" : "=r"(u) : "f"(f));
    return __uint_as_float(u);
}

// mma.sync tf32: operands are raw fp32 bits (HW truncates mantissa to tf32)
__device__ __forceinline__ void mma8(float* c, const float* a, const float* b) {
    const uint32_t* A = reinterpret_cast<const uint32_t*>(a);
    const uint32_t* Bp = reinterpret_cast<const uint32_t*>(b);
    asm volatile(
        "mma.sync.aligned.m16n8k8.row.col.f32.tf32.tf32.f32 "
        "{%0,%1,%2,%3}, {%4,%5,%6,%7}, {%8,%9}, {%0,%1,%2,%3};"
        : "+f"(c[0]), "+f"(c[1]), "+f"(c[2]), "+f"(c[3])
        : "r"(A[0]), "r"(A[1]), "r"(A[2]), "r"(A[3]), "r"(Bp[0]), "r"(Bp[1]));
}

// ---------------- epilogues ----------------
struct EpiQKV {   // write [B,NH,S,HD] layout, add bias
    const float* bias; float* dst;
    __device__ __forceinline__ void operator()(int r, int c, float v) const {
        int b = r >> 11, s = r & 2047, h = c >> 6, d = c & 63;
        dst[(((size_t)(b*NH_ + h))*S_ + s)*HD_ + d] = v + bias[c];
    }
};
struct EpiBiasRes {   // out = v + bias + residual   (N = H_)
    const float* bias; const float* res; float* dst;
    __device__ __forceinline__ void operator()(int r, int c, float v) const {
        size_t idx = (size_t)r*H_ + c;
        dst[idx] = v + bias[c] + res[idx];
    }
};
struct EpiGelu {      // out = gelu_tanh(v + bias)   (N = FF_)
    const float* bias; float* dst;
    __device__ __forceinline__ void operator()(int r, int c, float v) const {
        float x = v + bias[c];
        float t = tanhf(0.7978845608028654f * (x + 0.044715f * x * x * x));
        dst[(size_t)r*FF_ + c] = 0.5f * x * (1.0f + t);
    }
};

// ---------------- tf32 GEMM: C[M,N] = A[M,K] @ B[K,N] ----------------
// block tile 128x128x32, 128 threads = 4 warps (2x2), warp tile 64x64
// (LDS/mma = 1.0 vs 1.5 for the old 8-warp 64x32 config)
// double-buffered cp.async, natural smem layouts:
//   As[2][128][36]  (pad 4 -> frag banks grp*4+tig, conflict-free)
//   Bs[2][32][136]  (pad 8 -> frag banks tig*8+grp, conflict-free)
#define AS(buf,r,c) smem[(buf)*4608 + (r)*36 + (c)]
#define BS(buf,r,c) smem[9216 + (buf)*4352 + (r)*136 + (c)]

template <class Epi>
__global__ __launch_bounds__(128, 2) void gemm_tf32(
    const float* __restrict__ A, const float* __restrict__ Bm,
    int M, int N, int K, Epi epi)
{
    extern __shared__ float smem[];

    const int tid  = threadIdx.x;
    const int w    = tid >> 5, lane = tid & 31;
    const int grp  = lane >> 2, tig = lane & 3;
    const int warpM = w >> 1, warpN = w & 1;       // 2 x 2
    const int row0 = blockIdx.y * 128, col0 = blockIdx.x * 128;

    float c[4][8][4];
    #pragma unroll
    for (int i = 0; i < 4; i++)
        #pragma unroll
        for (int j = 0; j < 8; j++)
            #pragma unroll
            for (int l = 0; l < 4; l++) c[i][j][l] = 0.f;

    // chunk decompositions (16B), 128 threads x 8 chunks each:
    // A tile 128x32: 1024 chunks, row = c>>3, col = (c&7)*4
    // B tile 32x128: 1024 chunks, row = c>>5, col = (c&31)*4
    const int caC = (tid & 7) * 4;
    const int cbC = (tid & 31) * 4;

    auto load_tile = [&](int kk, int buf) {
        #pragma unroll
        for (int i = 0; i < 8; i++) {
            int rA = (tid + i*128) >> 3;
            cpa16(&AS(buf, rA, caC), A + (size_t)(row0 + rA)*K + kk + caC);
        }
        #pragma unroll
        for (int i = 0; i < 8; i++) {
            int rB = (tid + i*128) >> 5;
            cpa16(&BS(buf, rB, cbC), Bm + (size_t)(kk + rB)*N + col0 + cbC);
        }
        cp_commit();
    };

    const int ntk = K >> 5;
    load_tile(0, 0);

    #pragma unroll 1
    for (int t = 0; t < ntk; t++) {
        const int buf = t & 1;
        if (t + 1 < ntk) { load_tile((t+1) << 5, buf ^ 1); cp_wait1(); }
        else             { cp_wait0(); }
        __syncthreads();

        #pragma unroll
        for (int ks = 0; ks < 32; ks += 8) {
            float a[4][4];
            #pragma unroll
            for (int mt = 0; mt < 4; mt++) {
                int rb = warpM*64 + mt*16 + grp;
                a[mt][0] = rna(AS(buf, rb,   ks+tig));
                a[mt][1] = rna(AS(buf, rb+8, ks+tig));
                a[mt][2] = rna(AS(buf, rb,   ks+tig+4));
                a[mt][3] = rna(AS(buf, rb+8, ks+tig+4));
            }
            #pragma unroll
            for (int nt = 0; nt < 8; nt++) {
                int cb = warpN*64 + nt*8 + grp;
                float b[2];
                b[0] = rna(BS(buf, ks+tig,   cb));
                b[1] = rna(BS(buf, ks+tig+4, cb));
                #pragma unroll
                for (int mt = 0; mt < 4; mt++)
                    mma8(c[mt][nt], a[mt], b);
            }
        }
        __syncthreads();
    }

    #pragma unroll
    for (int mt = 0; mt < 4; mt++) {
        int r = row0 + warpM*64 + mt*16 + grp;
        #pragma unroll
        for (int nt = 0; nt < 8; nt++) {
            int cc = col0 + warpN*64 + nt*8 + tig*2;
            epi(r,     cc,   c[mt][nt][0]);
            epi(r,     cc+1, c[mt][nt][1]);
            epi(r+8,   cc,   c[mt][nt][2]);
            epi(r+8,   cc+1, c[mt][nt][3]);
        }
    }
}

// ---------------- flash attention ----------------
// q-tile 128 / block, 8 warps each own 16 q-rows x all 64 keys.
// Register softmax (quad shfl reductions), shfl-transposed P for PV mma.
// K/V double-buffered cp.async. Natural layouts:
//   Qs[128][68], Ks[2][64][68], Vs[2][64][72], msk[2][64]
#define QS(r,c)      sm[(r)*68 + (c)]
#define KS(buf,r,c)  sm[8704 + (buf)*4352 + (r)*68 + (c)]
#define VS(buf,r,c)  sm[17408 + (buf)*4608 + (r)*72 + (c)]
#define MSK(buf,i)   sm[26624 + (buf)*64 + (i)]
#define ATTN_SMEM (26752*4)

__global__ __launch_bounds__(256, 2) void attn_kernel(const float* __restrict__ mask)
{
    extern __shared__ float sm[];

    const int tid = threadIdx.x, w = tid >> 5, lane = tid & 31;
    const int grp = lane >> 2, tig = lane & 3;
    const int qt = blockIdx.x, bh = blockIdx.y;
    const int b = bh >> 4, h = bh & 15;

    const float* qg = g_q + (size_t)bh * S_ * HD_;
    const float* kg = g_k + (size_t)bh * S_ * HD_;
    const float* vg = g_v + (size_t)bh * S_ * HD_;

    // K/V chunk decomposition: 64x64 tile = 1024 chunks, row=c>>4, col=(c&15)*4
    const int kR[4] = { (tid)>>4, (tid+256)>>4, (tid+512)>>4, (tid+768)>>4 };
    const int kC = (tid & 15) * 4;

    auto load_kv = [&](int kt, int buf) {
        #pragma unroll
        for (int i = 0; i < 4; i++)
            cpa16(&KS(buf, kR[i], kC), kg + (size_t)(kt*64 + kR[i])*HD_ + kC);
        #pragma unroll
        for (int i = 0; i < 4; i++)
            cpa16(&VS(buf, kR[i], kC), vg + (size_t)(kt*64 + kR[i])*HD_ + kC);
        if (tid < 16)
            cpa16(&MSK(buf, tid*4), mask + (size_t)b*S_ + kt*64 + tid*4);
        cp_commit();
    };

    // prologue: Q tile (128x64 = 2048 chunks, 8/thread) + first KV in group 0
    {
        #pragma unroll
        for (int i = 0; i < 8; i++) {
            int cq = tid + i*256;
            int r = cq >> 4, c4 = (cq & 15) * 4;
            cpa16(&QS(r, c4), qg + (size_t)(qt*128 + r)*HD_ + c4);
        }
        load_kv(0, 0);
    }

    float o[8][4];
    #pragma unroll
    for (int i = 0; i < 8; i++)
        #pragma unroll
        for (int j = 0; j < 4; j++) o[i][j] = 0.f;
    float m0 = -1e30f, m1 = -1e30f, l0 = 0.f, l1 = 0.f;

    const float scale = 0.125f;   // 1/sqrt(64)
    const int wq = w * 16;
    const int qbase = lane & ~3;
    const int sA = qbase + (tig >> 1);
    const int sB = qbase + 2 + (tig >> 1);
    const bool odd = tig & 1;

    #pragma unroll 1
    for (int kt = 0; kt < S_/64; kt++) {
        const int buf = kt & 1;
        if (kt + 1 < S_/64) { load_kv(kt+1, buf ^ 1); cp_wait1(); }
        else                { cp_wait0(); }
        __syncthreads();

        // ---- scores = Q @ K^T ----
        float sc[8][4];
        #pragma unroll
        for (int i = 0; i < 8; i++)
            #pragma unroll
            for (int j = 0; j < 4; j++) sc[i][j] = 0.f;

        #pragma unroll
        for (int ks = 0; ks < 64; ks += 8) {
            float a[4];
            a[0] = QS(wq+grp,   ks+tig);
            a[1] = QS(wq+grp+8, ks+tig);
            a[2] = QS(wq+grp,   ks+tig+4);
            a[3] = QS(wq+grp+8, ks+tig+4);
            #pragma unroll
            for (int nt = 0; nt < 8; nt++) {
                float bfr[2];
                bfr[0] = KS(buf, nt*8+grp, ks+tig);
                bfr[1] = KS(buf, nt*8+grp, ks+tig+4);
                mma8(sc[nt], a, bfr);
            }
        }

        // ---- register softmax ----
        float rmax0 = -1e30f, rmax1 = -1e30f;
        #pragma unroll
        for (int nt = 0; nt < 8; nt++) {
            int c0 = nt*8 + tig*2;
            float mk0 = MSK(buf, c0), mk1 = MSK(buf, c0+1);
            sc[nt][0] = sc[nt][0]*scale + mk0;
            sc[nt][1] = sc[nt][1]*scale + mk1;
            sc[nt][2] = sc[nt][2]*scale + mk0;
            sc[nt][3] = sc[nt][3]*scale + mk1;
            rmax0 = fmaxf(rmax0, fmaxf(sc[nt][0], sc[nt][1]));
            rmax1 = fmaxf(rmax1, fmaxf(sc[nt][2], sc[nt][3]));
        }
        rmax0 = fmaxf(rmax0, __shfl_xor_sync(0xffffffffu, rmax0, 1));
        rmax0 = fmaxf(rmax0, __shfl_xor_sync(0xffffffffu, rmax0, 2));
        rmax1 = fmaxf(rmax1, __shfl_xor_sync(0xffffffffu, rmax1, 1));
        rmax1 = fmaxf(rmax1, __shfl_xor_sync(0xffffffffu, rmax1, 2));

        float mn0 = fmaxf(m0, rmax0), mn1 = fmaxf(m1, rmax1);
        float alpha0 = __expf(m0 - mn0), alpha1 = __expf(m1 - mn1);
        m0 = mn0; m1 = mn1;

        float sum0 = 0.f, sum1 = 0.f;
        #pragma unroll
        for (int nt = 0; nt < 8; nt++) {
            sc[nt][0] = __expf(sc[nt][0] - mn0);
            sc[nt][1] = __expf(sc[nt][1] - mn0);
            sc[nt][2] = __expf(sc[nt][2] - mn1);
            sc[nt][3] = __expf(sc[nt][3] - mn1);
            sum0 += sc[nt][0] + sc[nt][1];
            sum1 += sc[nt][2] + sc[nt][3];
        }
        sum0 += __shfl_xor_sync(0xffffffffu, sum0, 1);
        sum0 += __shfl_xor_sync(0xffffffffu, sum0, 2);
        sum1 += __shfl_xor_sync(0xffffffffu, sum1, 1);
        sum1 += __shfl_xor_sync(0xffffffffu, sum1, 2);
        l0 = l0*alpha0 + sum0;
        l1 = l1*alpha1 + sum1;

        #pragma unroll
        for (int nt = 0; nt < 8; nt++) {
            o[nt][0] *= alpha0; o[nt][1] *= alpha0;
            o[nt][2] *= alpha1; o[nt][3] *= alpha1;
        }

        // ---- O += P @ V (P via quad shfl-transpose into A-frag layout) ----
        #pragma unroll
        for (int kk = 0; kk < 8; kk++) {
            float u0 = __shfl_sync(0xffffffffu, sc[kk][0], sA);
            float u1 = __shfl_sync(0xffffffffu, sc[kk][1], sA);
            float u2 = __shfl_sync(0xffffffffu, sc[kk][2], sA);
            float u3 = __shfl_sync(0xffffffffu, sc[kk][3], sA);
            float w0 = __shfl_sync(0xffffffffu, sc[kk][0], sB);
            float w1 = __shfl_sync(0xffffffffu, sc[kk][1], sB);
            float w2 = __shfl_sync(0xffffffffu, sc[kk][2], sB);
            float w3 = __shfl_sync(0xffffffffu, sc[kk][3], sB);
            float a[4];
            a[0] = rna(odd ? u1 : u0);   // P[r0][8kk+tig]  (rna: P>0, RZ would bias down)
            a[1] = rna(odd ? u3 : u2);   // P[r1][8kk+tig]
            a[2] = rna(odd ? w1 : w0);   // P[r0][8kk+tig+4]
            a[3] = rna(odd ? w3 : w2);   // P[r1][8kk+tig+4]
            #pragma unroll
            for (int nt = 0; nt < 8; nt++) {
                float bfr[2];
                bfr[0] = VS(buf, kk*8+tig,   nt*8+grp);
                bfr[1] = VS(buf, kk*8+tig+4, nt*8+grp);
                mma8(o[nt], a, bfr);
            }
        }
        __syncthreads();
    }

    // ---- epilogue: O / l -> ctx [B,S,H] ----
    float inv0 = 1.f / l0, inv1 = 1.f / l1;
    int q0 = qt*128 + wq + grp, q1 = q0 + 8;
    #pragma unroll
    for (int nt = 0; nt < 8; nt++) {
        int d0 = nt*8 + tig*2;
        float2 v0 = make_float2(o[nt][0]*inv0, o[nt][1]*inv0);
        float2 v1 = make_float2(o[nt][2]*inv1, o[nt][3]*inv1);
        *reinterpret_cast<float2*>(g_ctx + ((size_t)(b*S_ + q0))*H_ + h*HD_ + d0) = v0;
        *reinterpret_cast<float2*>(g_ctx + ((size_t)(b*S_ + q1))*H_ + h*HD_ + d0) = v1;
    }
}

// ---------------- layernorm: one block per row ----------------
__global__ __launch_bounds__(256) void ln_kernel(
    const float* __restrict__ in, const float* __restrict__ g,
    const float* __restrict__ bb, float* __restrict__ out)
{
    __shared__ float red[18];
    const int row = blockIdx.x, tid = threadIdx.x;
    const float4 x = reinterpret_cast<const float4*>(in + (size_t)row*H_)[tid];
    float s  = x.x + x.y + x.z + x.w;
    float sq = x.x*x.x + x.y*x.y + x.z*x.z + x.w*x.w;
    #pragma unroll
    for (int off = 16; off > 0; off >>= 1) {
        s  += __shfl_xor_sync(0xffffffffu, s,  off);
        sq += __shfl_xor_sync(0xffffffffu, sq, off);
    }
    if ((tid & 31) == 0) { red[tid>>5] = s; red[8 + (tid>>5)] = sq; }
    __syncthreads();
    if (tid == 0) {
        float a = 0.f, c2 = 0.f;
        #pragma unroll
        for (int i = 0; i < 8; i++) { a += red[i]; c2 += red[8+i]; }
        red[16] = a; red[17] = c2;
    }
    __syncthreads();
    float mu  = red[16] * (1.f/1024.f);
    float var = red[17] * (1.f/1024.f) - mu*mu;
    float inv = rsqrtf(var + 1e-12f);
    float4 gv = reinterpret_cast<const float4*>(g)[tid];
    float4 bv = reinterpret_cast<const float4*>(bb)[tid];
    float4 o4;
    o4.x = (x.x - mu)*inv*gv.x + bv.x;
    o4.y = (x.y - mu)*inv*gv.y + bv.y;
    o4.z = (x.z - mu)*inv*gv.z + bv.z;
    o4.w = (x.w - mu)*inv*gv.w + bv.w;
    reinterpret_cast<float4*>(out + (size_t)row*H_)[tid] = o4;
}

// ---------------- launch ----------------
#define GEMM_SMEM (17920*4)

extern "C" void kernel_launch(void* const* d_in, const int* in_sizes, int n_in,
                              void* d_out, int out_size)
{
    (void)in_sizes; (void)n_in; (void)out_size;
    const float* x    = (const float*)d_in[0];
    const float* mask = (const float*)d_in[1];
    const float* Wq   = (const float*)d_in[2];
    const float* bq   = (const float*)d_in[3];
    const float* Wk   = (const float*)d_in[4];
    const float* bk   = (const float*)d_in[5];
    const float* Wv   = (const float*)d_in[6];
    const float* bv   = (const float*)d_in[7];
    const float* Wo   = (const float*)d_in[8];
    const float* bo   = (const float*)d_in[9];
    const float* ln1g = (const float*)d_in[10];
    const float* ln1b = (const float*)d_in[11];
    const float* W1   = (const float*)d_in[12];
    const float* b1   = (const float*)d_in[13];
    const float* W2   = (const float*)d_in[14];
    const float* b2   = (const float*)d_in[15];
    const float* ln2g = (const float*)d_in[16];
    const float* ln2b = (const float*)d_in[17];
    float* out = (float*)d_out;

    float *qp, *kp, *vp, *ctxp, *tmpp, *x1p, *ffp;
    cudaGetSymbolAddress((void**)&qp,   g_q);
    cudaGetSymbolAddress((void**)&kp,   g_k);
    cudaGetSymbolAddress((void**)&vp,   g_v);
    cudaGetSymbolAddress((void**)&ctxp, g_ctx);
    cudaGetSymbolAddress((void**)&tmpp, g_tmp);
    cudaGetSymbolAddress((void**)&x1p,  g_x1);
    cudaGetSymbolAddress((void**)&ffp,  g_ff);

    // set every call (idempotent; no static guards per harness rules)
    cudaFuncSetAttribute(gemm_tf32<EpiQKV>,     cudaFuncAttributeMaxDynamicSharedMemorySize, GEMM_SMEM);
    cudaFuncSetAttribute(gemm_tf32<EpiBiasRes>, cudaFuncAttributeMaxDynamicSharedMemorySize, GEMM_SMEM);
    cudaFuncSetAttribute(gemm_tf32<EpiGelu>,    cudaFuncAttributeMaxDynamicSharedMemorySize, GEMM_SMEM);
    cudaFuncSetAttribute(attn_kernel,           cudaFuncAttributeMaxDynamicSharedMemorySize, ATTN_SMEM);

    dim3 gblk(128);   // 4 warps, warp tile 64x64
    dim3 ablk(256);

    // QKV projections
    gemm_tf32<<<dim3(H_/128, MR_/128), gblk, GEMM_SMEM>>>(x, Wq, MR_, H_, H_, EpiQKV{bq, qp});
    gemm_tf32<<<dim3(H_/128, MR_/128), gblk, GEMM_SMEM>>>(x, Wk, MR_, H_, H_, EpiQKV{bk, kp});
    gemm_tf32<<<dim3(H_/128, MR_/128), gblk, GEMM_SMEM>>>(x, Wv, MR_, H_, H_, EpiQKV{bv, vp});

    // attention
    attn_kernel<<<dim3(S_/128, B_*NH_), ablk, ATTN_SMEM>>>(mask);

    // O projection + residual, LN1
    gemm_tf32<<<dim3(H_/128, MR_/128), gblk, GEMM_SMEM>>>(ctxp, Wo, MR_, H_, H_, EpiBiasRes{bo, x, tmpp});
    ln_kernel<<<MR_, 256>>>(tmpp, ln1g, ln1b, x1p);

    // FFN
    gemm_tf32<<<dim3(FF_/128, MR_/128), gblk, GEMM_SMEM>>>(x1p, W1, MR_, FF_, H_, EpiGelu{b1, ffp});
    gemm_tf32<<<dim3(H_/128, MR_/128), gblk, GEMM_SMEM>>>(ffp, W2, MR_, H_, FF_, EpiBiasRes{b2, x1p, tmpp});
    ln_kernel<<<MR_, 256>>>(tmpp, ln2g, ln2b, out);
}

// round 15
// speedup vs baseline: 1.0096x; 1.0096x over previous
#include <cuda_runtime.h>
#include <cstdint>
#include <math.h>

// ---------------- problem constants ----------------
#define B_   4
#define S_   2048
#define H_   1024
#define NH_  16
#define HD_  64
#define FF_  4096
#define MR_  (B_*S_)        // 8192 rows

// ---------------- scratch (device globals; no runtime allocation) ----------------
__device__ float g_q  [(size_t)MR_*H_];
__device__ float g_k  [(size_t)MR_*H_];
__device__ float g_v  [(size_t)MR_*H_];
__device__ float g_ctx[(size_t)MR_*H_];
__device__ float g_tmp[(size_t)MR_*H_];
__device__ float g_x1 [(size_t)MR_*H_];
__device__ float g_ff [(size_t)MR_*FF_];
// tf32-grid pre-rounded operands (so GEMM mainloop needs NO cvt: HW RZ of
// an already-rounded value is the identity)
__device__ float g_xr [(size_t)MR_*H_];
__device__ float g_x1r[(size_t)MR_*H_];
__device__ float g_wqr[(size_t)H_*H_];
__device__ float g_wkr[(size_t)H_*H_];
__device__ float g_wvr[(size_t)H_*H_];
__device__ float g_wor[(size_t)H_*H_];
__device__ float g_w1r[(size_t)H_*FF_];
__device__ float g_w2r[(size_t)FF_*H_];

// ---------------- helpers ----------------
__device__ __forceinline__ void cpa16(void* dst, const void* src) {
    uint32_t d = (uint32_t)__cvta_generic_to_shared(dst);
    asm volatile("cp.async.cg.shared.global [%0], [%1], 16;" :: "r"(d), "l"(src));
}
__device__ __forceinline__ void cp_commit() { asm volatile("cp.async.commit_group;"); }
__device__ __forceinline__ void cp_wait0()  { asm volatile("cp.async.wait_group 0;"); }
__device__ __forceinline__ void cp_wait1()  { asm volatile("cp.async.wait_group 1;"); }

// round-to-nearest tf32 (used in prepass/epilogues only — never in GEMM mainloop)
__device__ __forceinline__ float rna(float f) {
    uint32_t u;
    asm("cvt.rna.tf32.f32 %0, %1;" : "=r"(u) : "f"(f));
    return __uint_as_float(u);
}

// mma.sync tf32: operands are raw fp32 bits (HW truncates mantissa to tf32;
// identity for pre-rounded data)
__device__ __forceinline__ void mma8(float* c, const float* a, const float* b) {
    const uint32_t* A = reinterpret_cast<const uint32_t*>(a);
    const uint32_t* Bp = reinterpret_cast<const uint32_t*>(b);
    asm volatile(
        "mma.sync.aligned.m16n8k8.row.col.f32.tf32.tf32.f32 "
        "{%0,%1,%2,%3}, {%4,%5,%6,%7}, {%8,%9}, {%0,%1,%2,%3};"
        : "+f"(c[0]), "+f"(c[1]), "+f"(c[2]), "+f"(c[3])
        : "r"(A[0]), "r"(A[1]), "r"(A[2]), "r"(A[3]), "r"(Bp[0]), "r"(Bp[1]));
}

// ---------------- prepass: rna-round an array onto the tf32 grid ----------------
__global__ __launch_bounds__(256) void round_kernel(
    const float* __restrict__ in, float* __restrict__ out, int n4)
{
    int i = blockIdx.x * blockDim.x + threadIdx.x;
    if (i < n4) {
        float4 v = reinterpret_cast<const float4*>(in)[i];
        v.x = rna(v.x); v.y = rna(v.y); v.z = rna(v.z); v.w = rna(v.w);
        reinterpret_cast<float4*>(out)[i] = v;
    }
}

// ---------------- epilogues ----------------
struct EpiQKV {   // write [B,NH,S,HD] layout, add bias, tf32-round (feeds attn mma)
    const float* bias; float* dst;
    __device__ __forceinline__ void operator()(int r, int c, float v) const {
        int b = r >> 11, s = r & 2047, h = c >> 6, d = c & 63;
        dst[(((size_t)(b*NH_ + h))*S_ + s)*HD_ + d] = rna(v + bias[c]);
    }
};
struct EpiBiasRes {   // out = v + bias + residual (exact; feeds LN)  (N = H_)
    const float* bias; const float* res; float* dst;
    __device__ __forceinline__ void operator()(int r, int c, float v) const {
        size_t idx = (size_t)r*H_ + c;
        dst[idx] = v + bias[c] + res[idx];
    }
};
struct EpiGelu {      // out = rna(gelu_tanh(v + bias))  (feeds W2 GEMM)  (N = FF_)
    const float* bias; float* dst;
    __device__ __forceinline__ void operator()(int r, int c, float v) const {
        float x = v + bias[c];
        float t = tanhf(0.7978845608028654f * (x + 0.044715f * x * x * x));
        dst[(size_t)r*FF_ + c] = rna(0.5f * x * (1.0f + t));
    }
};

// ---------------- tf32 GEMM: C[M,N] = A[M,K] @ B[K,N] ----------------
// block tile 128x128x32, 256 threads = 8 warps (2x4), warp tile 64x32
// (measured-fast shape from round 5; 16 warps/SM at occ 2 for latency hiding)
// 3-stage cp.async pipeline, ONE __syncthreads per k-tile:
//   stage t+2 never aliases stages t / t+1, so the post-compute barrier is removable.
// natural smem layouts: As[3][128][36], Bs[3][32][136] (conflict-free frag banks)
#define AS(s,r,c) smem[(s)*8960 + (r)*36 + (c)]
#define BS(s,r,c) smem[(s)*8960 + 4608 + (r)*136 + (c)]

template <class Epi>
__global__ __launch_bounds__(256, 2) void gemm_tf32(
    const float* __restrict__ A, const float* __restrict__ Bm,
    int M, int N, int K, Epi epi)
{
    extern __shared__ float smem[];

    const int tid  = threadIdx.x;
    const int w    = tid >> 5, lane = tid & 31;
    const int grp  = lane >> 2, tig = lane & 3;
    const int warpM = w >> 2, warpN = w & 3;       // 2 x 4
    const int row0 = blockIdx.y * 128, col0 = blockIdx.x * 128;

    float c[4][4][4];
    #pragma unroll
    for (int i = 0; i < 4; i++)
        #pragma unroll
        for (int j = 0; j < 4; j++)
            #pragma unroll
            for (int l = 0; l < 4; l++) c[i][j][l] = 0.f;

    // chunk decompositions (16B):
    // A tile 128x32: 1024 chunks, row = c>>3, col = (c&7)*4
    // B tile 32x128: 1024 chunks, row = c>>5, col = (c&31)*4
    const int caR[4] = { (tid    )>>3, (tid+256)>>3, (tid+512)>>3, (tid+768)>>3 };
    const int caC = (tid & 7) * 4;
    const int cbR[4] = { (tid    )>>5, (tid+256)>>5, (tid+512)>>5, (tid+768)>>5 };
    const int cbC = (tid & 31) * 4;

    auto load_tile = [&](int kk, int s) {
        #pragma unroll
        for (int i = 0; i < 4; i++)
            cpa16(&AS(s, caR[i], caC), A + (size_t)(row0 + caR[i])*K + kk + caC);
        #pragma unroll
        for (int i = 0; i < 4; i++)
            cpa16(&BS(s, cbR[i], cbC), Bm + (size_t)(kk + cbR[i])*N + col0 + cbC);
        cp_commit();
    };

    const int ntk = K >> 5;      // K is always >= 1024 here, ntk >= 32
    load_tile(0, 0);
    load_tile(32, 1);

    #pragma unroll 1
    for (int t = 0; t < ntk; t++) {
        const int s = t % 3;
        if (t + 1 < ntk) cp_wait1();   // group t retired (t+1 may be in flight)
        else             cp_wait0();   // tail: last group must be retired
        __syncthreads();               // publish stage s to all warps
        if (t + 2 < ntk) load_tile((t+2) << 5, (t+2) % 3);

        #pragma unroll
        for (int ks = 0; ks < 32; ks += 8) {
            float a[4][4], b[4][2];
            #pragma unroll
            for (int mt = 0; mt < 4; mt++) {
                int rb = warpM*64 + mt*16 + grp;
                a[mt][0] = AS(s, rb,   ks+tig);
                a[mt][1] = AS(s, rb+8, ks+tig);
                a[mt][2] = AS(s, rb,   ks+tig+4);
                a[mt][3] = AS(s, rb+8, ks+tig+4);
            }
            #pragma unroll
            for (int nt = 0; nt < 4; nt++) {
                int cb = warpN*32 + nt*8 + grp;
                b[nt][0] = BS(s, ks+tig,   cb);
                b[nt][1] = BS(s, ks+tig+4, cb);
            }
            #pragma unroll
            for (int mt = 0; mt < 4; mt++)
                #pragma unroll
                for (int nt = 0; nt < 4; nt++)
                    mma8(c[mt][nt], a[mt], b[nt]);
        }
    }

    #pragma unroll
    for (int mt = 0; mt < 4; mt++) {
        int r = row0 + warpM*64 + mt*16 + grp;
        #pragma unroll
        for (int nt = 0; nt < 4; nt++) {
            int cc = col0 + warpN*32 + nt*8 + tig*2;
            epi(r,     cc,   c[mt][nt][0]);
            epi(r,     cc+1, c[mt][nt][1]);
            epi(r+8,   cc,   c[mt][nt][2]);
            epi(r+8,   cc+1, c[mt][nt][3]);
        }
    }
}

// ---------------- flash attention (unchanged from round-14 measured config) ----
// q-tile 128 / block, 8 warps each own 16 q-rows x all 64 keys.
// Register softmax (quad shfl reductions), shfl-transposed P for PV mma.
// K/V double-buffered cp.async. Natural layouts:
//   Qs[128][68], Ks[2][64][68], Vs[2][64][72], msk[2][64]
#define QS(r,c)      sm[(r)*68 + (c)]
#define KS(buf,r,c)  sm[8704 + (buf)*4352 + (r)*68 + (c)]
#define VS(buf,r,c)  sm[17408 + (buf)*4608 + (r)*72 + (c)]
#define MSK(buf,i)   sm[26624 + (buf)*64 + (i)]
#define ATTN_SMEM (26752*4)

__global__ __launch_bounds__(256, 2) void attn_kernel(const float* __restrict__ mask)
{
    extern __shared__ float sm[];

    const int tid = threadIdx.x, w = tid >> 5, lane = tid & 31;
    const int grp = lane >> 2, tig = lane & 3;
    const int qt = blockIdx.x, bh = blockIdx.y;
    const int b = bh >> 4, h = bh & 15;

    const float* qg = g_q + (size_t)bh * S_ * HD_;
    const float* kg = g_k + (size_t)bh * S_ * HD_;
    const float* vg = g_v + (size_t)bh * S_ * HD_;

    // K/V chunk decomposition: 64x64 tile = 1024 chunks, row=c>>4, col=(c&15)*4
    const int kR[4] = { (tid)>>4, (tid+256)>>4, (tid+512)>>4, (tid+768)>>4 };
    const int kC = (tid & 15) * 4;

    auto load_kv = [&](int kt, int buf) {
        #pragma unroll
        for (int i = 0; i < 4; i++)
            cpa16(&KS(buf, kR[i], kC), kg + (size_t)(kt*64 + kR[i])*HD_ + kC);
        #pragma unroll
        for (int i = 0; i < 4; i++)
            cpa16(&VS(buf, kR[i], kC), vg + (size_t)(kt*64 + kR[i])*HD_ + kC);
        if (tid < 16)
            cpa16(&MSK(buf, tid*4), mask + (size_t)b*S_ + kt*64 + tid*4);
        cp_commit();
    };

    // prologue: Q tile (128x64 = 2048 chunks, 8/thread) + first KV in group 0
    {
        #pragma unroll
        for (int i = 0; i < 8; i++) {
            int cq = tid + i*256;
            int r = cq >> 4, c4 = (cq & 15) * 4;
            cpa16(&QS(r, c4), qg + (size_t)(qt*128 + r)*HD_ + c4);
        }
        load_kv(0, 0);
    }

    float o[8][4];
    #pragma unroll
    for (int i = 0; i < 8; i++)
        #pragma unroll
        for (int j = 0; j < 4; j++) o[i][j] = 0.f;
    float m0 = -1e30f, m1 = -1e30f, l0 = 0.f, l1 = 0.f;

    const float scale = 0.125f;   // 1/sqrt(64)
    const int wq = w * 16;
    const int qbase = lane & ~3;
    const int sA = qbase + (tig >> 1);
    const int sB = qbase + 2 + (tig >> 1);
    const bool odd = tig & 1;

    #pragma unroll 1
    for (int kt = 0; kt < S_/64; kt++) {
        const int buf = kt & 1;
        if (kt + 1 < S_/64) { load_kv(kt+1, buf ^ 1); cp_wait1(); }
        else                { cp_wait0(); }
        __syncthreads();

        // ---- scores = Q @ K^T ----
        float sc[8][4];
        #pragma unroll
        for (int i = 0; i < 8; i++)
            #pragma unroll
            for (int j = 0; j < 4; j++) sc[i][j] = 0.f;

        #pragma unroll
        for (int ks = 0; ks < 64; ks += 8) {
            float a[4];
            a[0] = QS(wq+grp,   ks+tig);
            a[1] = QS(wq+grp+8, ks+tig);
            a[2] = QS(wq+grp,   ks+tig+4);
            a[3] = QS(wq+grp+8, ks+tig+4);
            #pragma unroll
            for (int nt = 0; nt < 8; nt++) {
                float bfr[2];
                bfr[0] = KS(buf, nt*8+grp, ks+tig);
                bfr[1] = KS(buf, nt*8+grp, ks+tig+4);
                mma8(sc[nt], a, bfr);
            }
        }

        // ---- register softmax ----
        float rmax0 = -1e30f, rmax1 = -1e30f;
        #pragma unroll
        for (int nt = 0; nt < 8; nt++) {
            int c0 = nt*8 + tig*2;
            float mk0 = MSK(buf, c0), mk1 = MSK(buf, c0+1);
            sc[nt][0] = sc[nt][0]*scale + mk0;
            sc[nt][1] = sc[nt][1]*scale + mk1;
            sc[nt][2] = sc[nt][2]*scale + mk0;
            sc[nt][3] = sc[nt][3]*scale + mk1;
            rmax0 = fmaxf(rmax0, fmaxf(sc[nt][0], sc[nt][1]));
            rmax1 = fmaxf(rmax1, fmaxf(sc[nt][2], sc[nt][3]));
        }
        rmax0 = fmaxf(rmax0, __shfl_xor_sync(0xffffffffu, rmax0, 1));
        rmax0 = fmaxf(rmax0, __shfl_xor_sync(0xffffffffu, rmax0, 2));
        rmax1 = fmaxf(rmax1, __shfl_xor_sync(0xffffffffu, rmax1, 1));
        rmax1 = fmaxf(rmax1, __shfl_xor_sync(0xffffffffu, rmax1, 2));

        float mn0 = fmaxf(m0, rmax0), mn1 = fmaxf(m1, rmax1);
        float alpha0 = __expf(m0 - mn0), alpha1 = __expf(m1 - mn1);
        m0 = mn0; m1 = mn1;

        float sum0 = 0.f, sum1 = 0.f;
        #pragma unroll
        for (int nt = 0; nt < 8; nt++) {
            sc[nt][0] = __expf(sc[nt][0] - mn0);
            sc[nt][1] = __expf(sc[nt][1] - mn0);
            sc[nt][2] = __expf(sc[nt][2] - mn1);
            sc[nt][3] = __expf(sc[nt][3] - mn1);
            sum0 += sc[nt][0] + sc[nt][1];
            sum1 += sc[nt][2] + sc[nt][3];
        }
        sum0 += __shfl_xor_sync(0xffffffffu, sum0, 1);
        sum0 += __shfl_xor_sync(0xffffffffu, sum0, 2);
        sum1 += __shfl_xor_sync(0xffffffffu, sum1, 1);
        sum1 += __shfl_xor_sync(0xffffffffu, sum1, 2);
        l0 = l0*alpha0 + sum0;
        l1 = l1*alpha1 + sum1;

        #pragma unroll
        for (int nt = 0; nt < 8; nt++) {
            o[nt][0] *= alpha0; o[nt][1] *= alpha0;
            o[nt][2] *= alpha1; o[nt][3] *= alpha1;
        }

        // ---- O += P @ V (P via quad shfl-transpose into A-frag layout) ----
        #pragma unroll
        for (int kk = 0; kk < 8; kk++) {
            float u0 = __shfl_sync(0xffffffffu, sc[kk][0], sA);
            float u1 = __shfl_sync(0xffffffffu, sc[kk][1], sA);
            float u2 = __shfl_sync(0xffffffffu, sc[kk][2], sA);
            float u3 = __shfl_sync(0xffffffffu, sc[kk][3], sA);
            float w0 = __shfl_sync(0xffffffffu, sc[kk][0], sB);
            float w1 = __shfl_sync(0xffffffffu, sc[kk][1], sB);
            float w2 = __shfl_sync(0xffffffffu, sc[kk][2], sB);
            float w3 = __shfl_sync(0xffffffffu, sc[kk][3], sB);
            float a[4];
            a[0] = rna(odd ? u1 : u0);   // P[r0][8kk+tig]  (rna: P>0, RZ would bias down)
            a[1] = rna(odd ? u3 : u2);   // P[r1][8kk+tig]
            a[2] = rna(odd ? w1 : w0);   // P[r0][8kk+tig+4]
            a[3] = rna(odd ? w3 : w2);   // P[r1][8kk+tig+4]
            #pragma unroll
            for (int nt = 0; nt < 8; nt++) {
                float bfr[2];
                bfr[0] = VS(buf, kk*8+tig,   nt*8+grp);
                bfr[1] = VS(buf, kk*8+tig+4, nt*8+grp);
                mma8(o[nt], a, bfr);
            }
        }
        __syncthreads();
    }

    // ---- epilogue: O / l -> ctx [B,S,H], tf32-rounded (feeds Wo GEMM) ----
    float inv0 = 1.f / l0, inv1 = 1.f / l1;
    int q0 = qt*128 + wq + grp, q1 = q0 + 8;
    #pragma unroll
    for (int nt = 0; nt < 8; nt++) {
        int d0 = nt*8 + tig*2;
        float2 v0 = make_float2(rna(o[nt][0]*inv0), rna(o[nt][1]*inv0));
        float2 v1 = make_float2(rna(o[nt][2]*inv1), rna(o[nt][3]*inv1));
        *reinterpret_cast<float2*>(g_ctx + ((size_t)(b*S_ + q0))*H_ + h*HD_ + d0) = v0;
        *reinterpret_cast<float2*>(g_ctx + ((size_t)(b*S_ + q1))*H_ + h*HD_ + d0) = v1;
    }
}

// ---------------- layernorm: one block per row; optional tf32-rounded copy ----
__global__ __launch_bounds__(256) void ln_kernel(
    const float* __restrict__ in, const float* __restrict__ g,
    const float* __restrict__ bb, float* __restrict__ out,
    float* __restrict__ out_r)
{
    __shared__ float red[18];
    const int row = blockIdx.x, tid = threadIdx.x;
    const float4 x = reinterpret_cast<const float4*>(in + (size_t)row*H_)[tid];
    float s  = x.x + x.y + x.z + x.w;
    float sq = x.x*x.x + x.y*x.y + x.z*x.z + x.w*x.w;
    #pragma unroll
    for (int off = 16; off > 0; off >>= 1) {
        s  += __shfl_xor_sync(0xffffffffu, s,  off);
        sq += __shfl_xor_sync(0xffffffffu, sq, off);
    }
    if ((tid & 31) == 0) { red[tid>>5] = s; red[8 + (tid>>5)] = sq; }
    __syncthreads();
    if (tid == 0) {
        float a = 0.f, c2 = 0.f;
        #pragma unroll
        for (int i = 0; i < 8; i++) { a += red[i]; c2 += red[8+i]; }
        red[16] = a; red[17] = c2;
    }
    __syncthreads();
    float mu  = red[16] * (1.f/1024.f);
    float var = red[17] * (1.f/1024.f) - mu*mu;
    float inv = rsqrtf(var + 1e-12f);
    float4 gv = reinterpret_cast<const float4*>(g)[tid];
    float4 bv = reinterpret_cast<const float4*>(bb)[tid];
    float4 o4;
    o4.x = (x.x - mu)*inv*gv.x + bv.x;
    o4.y = (x.y - mu)*inv*gv.y + bv.y;
    o4.z = (x.z - mu)*inv*gv.z + bv.z;
    o4.w = (x.w - mu)*inv*gv.w + bv.w;
    reinterpret_cast<float4*>(out + (size_t)row*H_)[tid] = o4;
    if (out_r) {
        float4 r4;
        r4.x = rna(o4.x); r4.y = rna(o4.y); r4.z = rna(o4.z); r4.w = rna(o4.w);
        reinterpret_cast<float4*>(out_r + (size_t)row*H_)[tid] = r4;
    }
}

// ---------------- launch ----------------
#define GEMM_SMEM (26880*4)   // 3 stages x (128x36 + 32x136) floats = 107520 B

extern "C" void kernel_launch(void* const* d_in, const int* in_sizes, int n_in,
                              void* d_out, int out_size)
{
    (void)in_sizes; (void)n_in; (void)out_size;
    const float* x    = (const float*)d_in[0];
    const float* mask = (const float*)d_in[1];
    const float* Wq   = (const float*)d_in[2];
    const float* bq   = (const float*)d_in[3];
    const float* Wk   = (const float*)d_in[4];
    const float* bk   = (const float*)d_in[5];
    const float* Wv   = (const float*)d_in[6];
    const float* bv   = (const float*)d_in[7];
    const float* Wo   = (const float*)d_in[8];
    const float* bo   = (const float*)d_in[9];
    const float* ln1g = (const float*)d_in[10];
    const float* ln1b = (const float*)d_in[11];
    const float* W1   = (const float*)d_in[12];
    const float* b1   = (const float*)d_in[13];
    const float* W2   = (const float*)d_in[14];
    const float* b2   = (const float*)d_in[15];
    const float* ln2g = (const float*)d_in[16];
    const float* ln2b = (const float*)d_in[17];
    float* out = (float*)d_out;

    float *qp, *kp, *vp, *ctxp, *tmpp, *x1p, *ffp;
    float *xrp, *x1rp, *wqr, *wkr, *wvr, *wor, *w1r, *w2r;
    cudaGetSymbolAddress((void**)&qp,   g_q);
    cudaGetSymbolAddress((void**)&kp,   g_k);
    cudaGetSymbolAddress((void**)&vp,   g_v);
    cudaGetSymbolAddress((void**)&ctxp, g_ctx);
    cudaGetSymbolAddress((void**)&tmpp, g_tmp);
    cudaGetSymbolAddress((void**)&x1p,  g_x1);
    cudaGetSymbolAddress((void**)&ffp,  g_ff);
    cudaGetSymbolAddress((void**)&xrp,  g_xr);
    cudaGetSymbolAddress((void**)&x1rp, g_x1r);
    cudaGetSymbolAddress((void**)&wqr,  g_wqr);
    cudaGetSymbolAddress((void**)&wkr,  g_wkr);
    cudaGetSymbolAddress((void**)&wvr,  g_wvr);
    cudaGetSymbolAddress((void**)&wor,  g_wor);
    cudaGetSymbolAddress((void**)&w1r,  g_w1r);
    cudaGetSymbolAddress((void**)&w2r,  g_w2r);

    // set every call (idempotent; no static guards per harness rules)
    cudaFuncSetAttribute(gemm_tf32<EpiQKV>,     cudaFuncAttributeMaxDynamicSharedMemorySize, GEMM_SMEM);
    cudaFuncSetAttribute(gemm_tf32<EpiBiasRes>, cudaFuncAttributeMaxDynamicSharedMemorySize, GEMM_SMEM);
    cudaFuncSetAttribute(gemm_tf32<EpiGelu>,    cudaFuncAttributeMaxDynamicSharedMemorySize, GEMM_SMEM);
    cudaFuncSetAttribute(attn_kernel,           cudaFuncAttributeMaxDynamicSharedMemorySize, ATTN_SMEM);

    dim3 blk(256);

    // prepass: tf32-round x and all weight matrices (HW RZ then = identity)
    {
        const int xh4 = MR_*H_/4, hh4 = H_*H_/4, hf4 = H_*FF_/4;
        round_kernel<<<(xh4+255)/256, blk>>>(x,  xrp, xh4);
        round_kernel<<<(hh4+255)/256, blk>>>(Wq, wqr, hh4);
        round_kernel<<<(hh4+255)/256, blk>>>(Wk, wkr, hh4);
        round_kernel<<<(hh4+255)/256, blk>>>(Wv, wvr, hh4);
        round_kernel<<<(hh4+255)/256, blk>>>(Wo, wor, hh4);
        round_kernel<<<(hf4+255)/256, blk>>>(W1, w1r, hf4);
        round_kernel<<<(hf4+255)/256, blk>>>(W2, w2r, hf4);
    }

    // QKV projections (pre-rounded operands; EpiQKV rounds outputs for attn)
    gemm_tf32<<<dim3(H_/128, MR_/128), blk, GEMM_SMEM>>>(xrp, wqr, MR_, H_, H_, EpiQKV{bq, qp});
    gemm_tf32<<<dim3(H_/128, MR_/128), blk, GEMM_SMEM>>>(xrp, wkr, MR_, H_, H_, EpiQKV{bk, kp});
    gemm_tf32<<<dim3(H_/128, MR_/128), blk, GEMM_SMEM>>>(xrp, wvr, MR_, H_, H_, EpiQKV{bv, vp});

    // attention (ctx written tf32-rounded)
    attn_kernel<<<dim3(S_/128, B_*NH_), blk, ATTN_SMEM>>>(mask);

    // O projection + residual (exact), LN1 (exact out + rounded copy for FFN1)
    gemm_tf32<<<dim3(H_/128, MR_/128), blk, GEMM_SMEM>>>(ctxp, wor, MR_, H_, H_, EpiBiasRes{bo, x, tmpp});
    ln_kernel<<<MR_, 256>>>(tmpp, ln1g, ln1b, x1p, x1rp);

    // FFN (EpiGelu rounds ff for W2 GEMM; residual uses exact x1)
    gemm_tf32<<<dim3(FF_/128, MR_/128), blk, GEMM_SMEM>>>(x1rp, w1r, MR_, FF_, H_, EpiGelu{b1, ffp});
    gemm_tf32<<<dim3(H_/128, MR_/128), blk, GEMM_SMEM>>>(ffp, w2r, MR_, H_, FF_, EpiBiasRes{b2, x1p, tmpp});
    ln_kernel<<<MR_, 256>>>(tmpp, ln2g, ln2b, out, nullptr);
}

// round 16
// speedup vs baseline: 1.0827x; 1.0725x over previous
#include <cuda_runtime.h>
#include <cstdint>
#include <math.h>

// ---------------- problem constants ----------------
#define B_   4
#define S_   2048
#define H_   1024
#define NH_  16
#define HD_  64
#define FF_  4096
#define MR_  (B_*S_)        // 8192 rows

// ---------------- scratch (device globals; no runtime allocation) ----------------
__device__ float g_q   [(size_t)MR_*H_];
__device__ float g_k   [(size_t)MR_*H_];
__device__ float g_v   [(size_t)MR_*H_];
__device__ float g_ctx [(size_t)MR_*H_];
__device__ float g_tmp [(size_t)MR_*H_];
__device__ float g_x1  [(size_t)MR_*H_];
__device__ float g_x1r [(size_t)MR_*H_];
__device__ float g_ff  [(size_t)MR_*FF_];
// tf32-grid pre-rounded weights (HW RZ of pre-rounded data = identity -> no cvt in mainloop)
__device__ float g_wqkv[(size_t)H_*3*H_];   // [K=1024][N=3072] = Wq|Wk|Wv columns
__device__ float g_wor [(size_t)H_*H_];
__device__ float g_w1r [(size_t)H_*FF_];
__device__ float g_w2r [(size_t)FF_*H_];

// ---------------- helpers ----------------
__device__ __forceinline__ void cpa16(void* dst, const void* src) {
    uint32_t d = (uint32_t)__cvta_generic_to_shared(dst);
    asm volatile("cp.async.cg.shared.global [%0], [%1], 16;" :: "r"(d), "l"(src));
}
__device__ __forceinline__ void cp_commit() { asm volatile("cp.async.commit_group;"); }
__device__ __forceinline__ void cp_wait0()  { asm volatile("cp.async.wait_group 0;"); }
__device__ __forceinline__ void cp_wait1()  { asm volatile("cp.async.wait_group 1;"); }

// round-to-nearest tf32 (prepass/epilogues only — never in GEMM mainloop)
__device__ __forceinline__ float rna(float f) {
    uint32_t u;
    asm("cvt.rna.tf32.f32 %0, %1;" : "=r"(u) : "f"(f));
    return __uint_as_float(u);
}

// mma.sync tf32: raw fp32 bits (HW RZ; identity on pre-rounded operands)
__device__ __forceinline__ void mma8(float* c, const float* a, const float* b) {
    const uint32_t* A = reinterpret_cast<const uint32_t*>(a);
    const uint32_t* Bp = reinterpret_cast<const uint32_t*>(b);
    asm volatile(
        "mma.sync.aligned.m16n8k8.row.col.f32.tf32.tf32.f32 "
        "{%0,%1,%2,%3}, {%4,%5,%6,%7}, {%8,%9}, {%0,%1,%2,%3};"
        : "+f"(c[0]), "+f"(c[1]), "+f"(c[2]), "+f"(c[3])
        : "r"(A[0]), "r"(A[1]), "r"(A[2]), "r"(A[3]), "r"(Bp[0]), "r"(Bp[1]));
}

// ---------------- prepass kernels ----------------
// round in[n4*4] onto tf32 grid -> out
__global__ __launch_bounds__(256) void round_kernel(
    const float* __restrict__ in, float* __restrict__ out, int n4)
{
    int i = blockIdx.x * blockDim.x + threadIdx.x;
    if (i < n4) {
        float4 v = reinterpret_cast<const float4*>(in)[i];
        v.x = rna(v.x); v.y = rna(v.y); v.z = rna(v.z); v.w = rna(v.w);
        reinterpret_cast<float4*>(out)[i] = v;
    }
}
// round W[1024][1024] into g_wqkv[k][off + n] (ld 3072)
__global__ __launch_bounds__(256) void round_concat_kernel(
    const float* __restrict__ in, float* __restrict__ out, int off)
{
    int i = blockIdx.x * blockDim.x + threadIdx.x;   // over H_*H_/4
    if (i < H_*H_/4) {
        int k = i >> 8, nc = (i & 255) * 4;
        float4 v = reinterpret_cast<const float4*>(in)[i];
        v.x = rna(v.x); v.y = rna(v.y); v.z = rna(v.z); v.w = rna(v.w);
        *reinterpret_cast<float4*>(out + (size_t)k*(3*H_) + off + nc) = v;
    }
}

// ---------------- epilogues ----------------
struct EpiQKV3 {  // fused QKV: c in [0,3072); route to q/k/v [B,NH,S,HD], bias, rna
    const float* bias0; const float* bias1; const float* bias2;
    float* dst0; float* dst1; float* dst2;
    __device__ __forceinline__ void operator()(int r, int c, float v) const {
        int j = c >> 10, c1 = c & 1023;
        const float* bias = (j == 0) ? bias0 : (j == 1) ? bias1 : bias2;
        float*       dst  = (j == 0) ? dst0  : (j == 1) ? dst1  : dst2;
        int b = r >> 11, s = r & 2047, h = c1 >> 6, d = c1 & 63;
        dst[(((size_t)(b*NH_ + h))*S_ + s)*HD_ + d] = rna(v + bias[c1]);
    }
};
struct EpiBiasRes {   // out = v + bias + residual (exact; feeds LN)  (N = H_)
    const float* bias; const float* res; float* dst;
    __device__ __forceinline__ void operator()(int r, int c, float v) const {
        size_t idx = (size_t)r*H_ + c;
        dst[idx] = v + bias[c] + res[idx];
    }
};
struct EpiGelu {      // out = rna(gelu_tanh(v + bias))  (feeds W2 GEMM)  (N = FF_)
    const float* bias; float* dst;
    __device__ __forceinline__ void operator()(int r, int c, float v) const {
        float x = v + bias[c];
        float t = tanhf(0.7978845608028654f * (x + 0.044715f * x * x * x));
        dst[(size_t)r*FF_ + c] = rna(0.5f * x * (1.0f + t));
    }
};

// ---------------- tf32 GEMM: C[M,N] = A[M,K] @ B[K,N] ----------------
// R5-measured shape: block 128x128x32, 256 threads = 8 warps (2x4), warp 64x32,
// 2-stage cp.async double buffer. Natural smem layouts:
//   As[2][128][36] (pad 4 -> frag banks grp*4+tig), Bs[2][32][136] (pad 8)
#define AS(buf,r,c) smem[(buf)*4608 + (r)*36 + (c)]
#define BS(buf,r,c) smem[9216 + (buf)*4352 + (r)*136 + (c)]

template <class Epi>
__global__ __launch_bounds__(256, 2) void gemm_tf32(
    const float* __restrict__ A, const float* __restrict__ Bm,
    int M, int N, int K, Epi epi)
{
    extern __shared__ float smem[];

    const int tid  = threadIdx.x;
    const int w    = tid >> 5, lane = tid & 31;
    const int grp  = lane >> 2, tig = lane & 3;
    const int warpM = w >> 2, warpN = w & 3;       // 2 x 4
    const int row0 = blockIdx.y * 128, col0 = blockIdx.x * 128;

    float c[4][4][4];
    #pragma unroll
    for (int i = 0; i < 4; i++)
        #pragma unroll
        for (int j = 0; j < 4; j++)
            #pragma unroll
            for (int l = 0; l < 4; l++) c[i][j][l] = 0.f;

    // chunk decompositions (16B):
    // A tile 128x32: 1024 chunks, row = c>>3, col = (c&7)*4
    // B tile 32x128: 1024 chunks, row = c>>5, col = (c&31)*4
    const int caR[4] = { (tid    )>>3, (tid+256)>>3, (tid+512)>>3, (tid+768)>>3 };
    const int caC = (tid & 7) * 4;
    const int cbR[4] = { (tid    )>>5, (tid+256)>>5, (tid+512)>>5, (tid+768)>>5 };
    const int cbC = (tid & 31) * 4;

    auto load_tile = [&](int kk, int buf) {
        #pragma unroll
        for (int i = 0; i < 4; i++)
            cpa16(&AS(buf, caR[i], caC), A + (size_t)(row0 + caR[i])*K + kk + caC);
        #pragma unroll
        for (int i = 0; i < 4; i++)
            cpa16(&BS(buf, cbR[i], cbC), Bm + (size_t)(kk + cbR[i])*N + col0 + cbC);
        cp_commit();
    };

    const int ntk = K >> 5;
    load_tile(0, 0);

    #pragma unroll 1
    for (int t = 0; t < ntk; t++) {
        const int buf = t & 1;
        if (t + 1 < ntk) { load_tile((t+1) << 5, buf ^ 1); cp_wait1(); }
        else             { cp_wait0(); }
        __syncthreads();

        #pragma unroll
        for (int ks = 0; ks < 32; ks += 8) {
            float a[4][4], b[4][2];
            #pragma unroll
            for (int mt = 0; mt < 4; mt++) {
                int rb = warpM*64 + mt*16 + grp;
                a[mt][0] = AS(buf, rb,   ks+tig);
                a[mt][1] = AS(buf, rb+8, ks+tig);
                a[mt][2] = AS(buf, rb,   ks+tig+4);
                a[mt][3] = AS(buf, rb+8, ks+tig+4);
            }
            #pragma unroll
            for (int nt = 0; nt < 4; nt++) {
                int cb = warpN*32 + nt*8 + grp;
                b[nt][0] = BS(buf, ks+tig,   cb);
                b[nt][1] = BS(buf, ks+tig+4, cb);
            }
            #pragma unroll
            for (int mt = 0; mt < 4; mt++)
                #pragma unroll
                for (int nt = 0; nt < 4; nt++)
                    mma8(c[mt][nt], a[mt], b[nt]);
        }
        __syncthreads();
    }

    #pragma unroll
    for (int mt = 0; mt < 4; mt++) {
        int r = row0 + warpM*64 + mt*16 + grp;
        #pragma unroll
        for (int nt = 0; nt < 4; nt++) {
            int cc = col0 + warpN*32 + nt*8 + tig*2;
            epi(r,     cc,   c[mt][nt][0]);
            epi(r,     cc+1, c[mt][nt][1]);
            epi(r+8,   cc,   c[mt][nt][2]);
            epi(r+8,   cc+1, c[mt][nt][3]);
        }
    }
}

// ---------------- flash attention (measured config; ctx written tf32-rounded) --
#define QS(r,c)      sm[(r)*68 + (c)]
#define KS(buf,r,c)  sm[8704 + (buf)*4352 + (r)*68 + (c)]
#define VS(buf,r,c)  sm[17408 + (buf)*4608 + (r)*72 + (c)]
#define MSK(buf,i)   sm[26624 + (buf)*64 + (i)]
#define ATTN_SMEM (26752*4)

__global__ __launch_bounds__(256, 2) void attn_kernel(const float* __restrict__ mask)
{
    extern __shared__ float sm[];

    const int tid = threadIdx.x, w = tid >> 5, lane = tid & 31;
    const int grp = lane >> 2, tig = lane & 3;
    const int qt = blockIdx.x, bh = blockIdx.y;
    const int b = bh >> 4, h = bh & 15;

    const float* qg = g_q + (size_t)bh * S_ * HD_;
    const float* kg = g_k + (size_t)bh * S_ * HD_;
    const float* vg = g_v + (size_t)bh * S_ * HD_;

    const int kR[4] = { (tid)>>4, (tid+256)>>4, (tid+512)>>4, (tid+768)>>4 };
    const int kC = (tid & 15) * 4;

    auto load_kv = [&](int kt, int buf) {
        #pragma unroll
        for (int i = 0; i < 4; i++)
            cpa16(&KS(buf, kR[i], kC), kg + (size_t)(kt*64 + kR[i])*HD_ + kC);
        #pragma unroll
        for (int i = 0; i < 4; i++)
            cpa16(&VS(buf, kR[i], kC), vg + (size_t)(kt*64 + kR[i])*HD_ + kC);
        if (tid < 16)
            cpa16(&MSK(buf, tid*4), mask + (size_t)b*S_ + kt*64 + tid*4);
        cp_commit();
    };

    {
        #pragma unroll
        for (int i = 0; i < 8; i++) {
            int cq = tid + i*256;
            int r = cq >> 4, c4 = (cq & 15) * 4;
            cpa16(&QS(r, c4), qg + (size_t)(qt*128 + r)*HD_ + c4);
        }
        load_kv(0, 0);
    }

    float o[8][4];
    #pragma unroll
    for (int i = 0; i < 8; i++)
        #pragma unroll
        for (int j = 0; j < 4; j++) o[i][j] = 0.f;
    float m0 = -1e30f, m1 = -1e30f, l0 = 0.f, l1 = 0.f;

    const float scale = 0.125f;
    const int wq = w * 16;
    const int qbase = lane & ~3;
    const int sA = qbase + (tig >> 1);
    const int sB = qbase + 2 + (tig >> 1);
    const bool odd = tig & 1;

    #pragma unroll 1
    for (int kt = 0; kt < S_/64; kt++) {
        const int buf = kt & 1;
        if (kt + 1 < S_/64) { load_kv(kt+1, buf ^ 1); cp_wait1(); }
        else                { cp_wait0(); }
        __syncthreads();

        float sc[8][4];
        #pragma unroll
        for (int i = 0; i < 8; i++)
            #pragma unroll
            for (int j = 0; j < 4; j++) sc[i][j] = 0.f;

        #pragma unroll
        for (int ks = 0; ks < 64; ks += 8) {
            float a[4];
            a[0] = QS(wq+grp,   ks+tig);
            a[1] = QS(wq+grp+8, ks+tig);
            a[2] = QS(wq+grp,   ks+tig+4);
            a[3] = QS(wq+grp+8, ks+tig+4);
            #pragma unroll
            for (int nt = 0; nt < 8; nt++) {
                float bfr[2];
                bfr[0] = KS(buf, nt*8+grp, ks+tig);
                bfr[1] = KS(buf, nt*8+grp, ks+tig+4);
                mma8(sc[nt], a, bfr);
            }
        }

        float rmax0 = -1e30f, rmax1 = -1e30f;
        #pragma unroll
        for (int nt = 0; nt < 8; nt++) {
            int c0 = nt*8 + tig*2;
            float mk0 = MSK(buf, c0), mk1 = MSK(buf, c0+1);
            sc[nt][0] = sc[nt][0]*scale + mk0;
            sc[nt][1] = sc[nt][1]*scale + mk1;
            sc[nt][2] = sc[nt][2]*scale + mk0;
            sc[nt][3] = sc[nt][3]*scale + mk1;
            rmax0 = fmaxf(rmax0, fmaxf(sc[nt][0], sc[nt][1]));
            rmax1 = fmaxf(rmax1, fmaxf(sc[nt][2], sc[nt][3]));
        }
        rmax0 = fmaxf(rmax0, __shfl_xor_sync(0xffffffffu, rmax0, 1));
        rmax0 = fmaxf(rmax0, __shfl_xor_sync(0xffffffffu, rmax0, 2));
        rmax1 = fmaxf(rmax1, __shfl_xor_sync(0xffffffffu, rmax1, 1));
        rmax1 = fmaxf(rmax1, __shfl_xor_sync(0xffffffffu, rmax1, 2));

        float mn0 = fmaxf(m0, rmax0), mn1 = fmaxf(m1, rmax1);
        float alpha0 = __expf(m0 - mn0), alpha1 = __expf(m1 - mn1);
        m0 = mn0; m1 = mn1;

        float sum0 = 0.f, sum1 = 0.f;
        #pragma unroll
        for (int nt = 0; nt < 8; nt++) {
            sc[nt][0] = __expf(sc[nt][0] - mn0);
            sc[nt][1] = __expf(sc[nt][1] - mn0);
            sc[nt][2] = __expf(sc[nt][2] - mn1);
            sc[nt][3] = __expf(sc[nt][3] - mn1);
            sum0 += sc[nt][0] + sc[nt][1];
            sum1 += sc[nt][2] + sc[nt][3];
        }
        sum0 += __shfl_xor_sync(0xffffffffu, sum0, 1);
        sum0 += __shfl_xor_sync(0xffffffffu, sum0, 2);
        sum1 += __shfl_xor_sync(0xffffffffu, sum1, 1);
        sum1 += __shfl_xor_sync(0xffffffffu, sum1, 2);
        l0 = l0*alpha0 + sum0;
        l1 = l1*alpha1 + sum1;

        #pragma unroll
        for (int nt = 0; nt < 8; nt++) {
            o[nt][0] *= alpha0; o[nt][1] *= alpha0;
            o[nt][2] *= alpha1; o[nt][3] *= alpha1;
        }

        #pragma unroll
        for (int kk = 0; kk < 8; kk++) {
            float u0 = __shfl_sync(0xffffffffu, sc[kk][0], sA);
            float u1 = __shfl_sync(0xffffffffu, sc[kk][1], sA);
            float u2 = __shfl_sync(0xffffffffu, sc[kk][2], sA);
            float u3 = __shfl_sync(0xffffffffu, sc[kk][3], sA);
            float w0 = __shfl_sync(0xffffffffu, sc[kk][0], sB);
            float w1 = __shfl_sync(0xffffffffu, sc[kk][1], sB);
            float w2 = __shfl_sync(0xffffffffu, sc[kk][2], sB);
            float w3 = __shfl_sync(0xffffffffu, sc[kk][3], sB);
            float a[4];
            a[0] = rna(odd ? u1 : u0);
            a[1] = rna(odd ? u3 : u2);
            a[2] = rna(odd ? w1 : w0);
            a[3] = rna(odd ? w3 : w2);
            #pragma unroll
            for (int nt = 0; nt < 8; nt++) {
                float bfr[2];
                bfr[0] = VS(buf, kk*8+tig,   nt*8+grp);
                bfr[1] = VS(buf, kk*8+tig+4, nt*8+grp);
                mma8(o[nt], a, bfr);
            }
        }
        __syncthreads();
    }

    float inv0 = 1.f / l0, inv1 = 1.f / l1;
    int q0 = qt*128 + wq + grp, q1 = q0 + 8;
    #pragma unroll
    for (int nt = 0; nt < 8; nt++) {
        int d0 = nt*8 + tig*2;
        float2 v0 = make_float2(rna(o[nt][0]*inv0), rna(o[nt][1]*inv0));
        float2 v1 = make_float2(rna(o[nt][2]*inv1), rna(o[nt][3]*inv1));
        *reinterpret_cast<float2*>(g_ctx + ((size_t)(b*S_ + q0))*H_ + h*HD_ + d0) = v0;
        *reinterpret_cast<float2*>(g_ctx + ((size_t)(b*S_ + q1))*H_ + h*HD_ + d0) = v1;
    }
}

// ---------------- layernorm: one block per row; optional tf32-rounded copy ----
__global__ __launch_bounds__(256) void ln_kernel(
    const float* __restrict__ in, const float* __restrict__ g,
    const float* __restrict__ bb, float* __restrict__ out,
    float* __restrict__ out_r)
{
    __shared__ float red[18];
    const int row = blockIdx.x, tid = threadIdx.x;
    const float4 x = reinterpret_cast<const float4*>(in + (size_t)row*H_)[tid];
    float s  = x.x + x.y + x.z + x.w;
    float sq = x.x*x.x + x.y*x.y + x.z*x.z + x.w*x.w;
    #pragma unroll
    for (int off = 16; off > 0; off >>= 1) {
        s  += __shfl_xor_sync(0xffffffffu, s,  off);
        sq += __shfl_xor_sync(0xffffffffu, sq, off);
    }
    if ((tid & 31) == 0) { red[tid>>5] = s; red[8 + (tid>>5)] = sq; }
    __syncthreads();
    if (tid == 0) {
        float a = 0.f, c2 = 0.f;
        #pragma unroll
        for (int i = 0; i < 8; i++) { a += red[i]; c2 += red[8+i]; }
        red[16] = a; red[17] = c2;
    }
    __syncthreads();
    float mu  = red[16] * (1.f/1024.f);
    float var = red[17] * (1.f/1024.f) - mu*mu;
    float inv = rsqrtf(var + 1e-12f);
    float4 gv = reinterpret_cast<const float4*>(g)[tid];
    float4 bv = reinterpret_cast<const float4*>(bb)[tid];
    float4 o4;
    o4.x = (x.x - mu)*inv*gv.x + bv.x;
    o4.y = (x.y - mu)*inv*gv.y + bv.y;
    o4.z = (x.z - mu)*inv*gv.z + bv.z;
    o4.w = (x.w - mu)*inv*gv.w + bv.w;
    reinterpret_cast<float4*>(out + (size_t)row*H_)[tid] = o4;
    if (out_r) {
        float4 r4;
        r4.x = rna(o4.x); r4.y = rna(o4.y); r4.z = rna(o4.z); r4.w = rna(o4.w);
        reinterpret_cast<float4*>(out_r + (size_t)row*H_)[tid] = r4;
    }
}

// ---------------- launch ----------------
#define GEMM_SMEM (17920*4)   // 2-stage: 2 x (128x36 + 32x136) floats = 71680 B

extern "C" void kernel_launch(void* const* d_in, const int* in_sizes, int n_in,
                              void* d_out, int out_size)
{
    (void)in_sizes; (void)n_in; (void)out_size;
    const float* x    = (const float*)d_in[0];
    const float* mask = (const float*)d_in[1];
    const float* Wq   = (const float*)d_in[2];
    const float* bq   = (const float*)d_in[3];
    const float* Wk   = (const float*)d_in[4];
    const float* bk   = (const float*)d_in[5];
    const float* Wv   = (const float*)d_in[6];
    const float* bv   = (const float*)d_in[7];
    const float* Wo   = (const float*)d_in[8];
    const float* bo   = (const float*)d_in[9];
    const float* ln1g = (const float*)d_in[10];
    const float* ln1b = (const float*)d_in[11];
    const float* W1   = (const float*)d_in[12];
    const float* b1   = (const float*)d_in[13];
    const float* W2   = (const float*)d_in[14];
    const float* b2   = (const float*)d_in[15];
    const float* ln2g = (const float*)d_in[16];
    const float* ln2b = (const float*)d_in[17];
    float* out = (float*)d_out;

    float *qp, *kp, *vp, *ctxp, *tmpp, *x1p, *x1rp, *ffp;
    float *wqkv, *wor, *w1r, *w2r;
    cudaGetSymbolAddress((void**)&qp,   g_q);
    cudaGetSymbolAddress((void**)&kp,   g_k);
    cudaGetSymbolAddress((void**)&vp,   g_v);
    cudaGetSymbolAddress((void**)&ctxp, g_ctx);
    cudaGetSymbolAddress((void**)&tmpp, g_tmp);
    cudaGetSymbolAddress((void**)&x1p,  g_x1);
    cudaGetSymbolAddress((void**)&x1rp, g_x1r);
    cudaGetSymbolAddress((void**)&ffp,  g_ff);
    cudaGetSymbolAddress((void**)&wqkv, g_wqkv);
    cudaGetSymbolAddress((void**)&wor,  g_wor);
    cudaGetSymbolAddress((void**)&w1r,  g_w1r);
    cudaGetSymbolAddress((void**)&w2r,  g_w2r);

    // set every call (idempotent; no static guards per harness rules)
    cudaFuncSetAttribute(gemm_tf32<EpiQKV3>,    cudaFuncAttributeMaxDynamicSharedMemorySize, GEMM_SMEM);
    cudaFuncSetAttribute(gemm_tf32<EpiBiasRes>, cudaFuncAttributeMaxDynamicSharedMemorySize, GEMM_SMEM);
    cudaFuncSetAttribute(gemm_tf32<EpiGelu>,    cudaFuncAttributeMaxDynamicSharedMemorySize, GEMM_SMEM);
    cudaFuncSetAttribute(attn_kernel,           cudaFuncAttributeMaxDynamicSharedMemorySize, ATTN_SMEM);

    dim3 blk(256);

    // prepass: tf32-round weights (B operands). x stays raw (half-bias accepted:
    // uniform multiplicative on q/k/v; cancelled by softmax scale-invariance + LN).
    {
        const int hh4 = H_*H_/4, hf4 = H_*FF_/4;
        round_concat_kernel<<<(hh4+255)/256, blk>>>(Wq, wqkv, 0);
        round_concat_kernel<<<(hh4+255)/256, blk>>>(Wk, wqkv, H_);
        round_concat_kernel<<<(hh4+255)/256, blk>>>(Wv, wqkv, 2*H_);
        round_kernel<<<(hh4+255)/256, blk>>>(Wo, wor, hh4);
        round_kernel<<<(hf4+255)/256, blk>>>(W1, w1r, hf4);
        round_kernel<<<(hf4+255)/256, blk>>>(W2, w2r, hf4);
    }

    // fused QKV projection: C[8192, 3072] = x @ [Wq|Wk|Wv]
    gemm_tf32<<<dim3(3*H_/128, MR_/128), blk, GEMM_SMEM>>>(
        x, wqkv, MR_, 3*H_, H_, EpiQKV3{bq, bk, bv, qp, kp, vp});

    // attention (ctx written tf32-rounded)
    attn_kernel<<<dim3(S_/128, B_*NH_), blk, ATTN_SMEM>>>(mask);

    // O projection + residual (exact), LN1 (exact out + rounded copy for FFN1)
    gemm_tf32<<<dim3(H_/128, MR_/128), blk, GEMM_SMEM>>>(ctxp, wor, MR_, H_, H_, EpiBiasRes{bo, x, tmpp});
    ln_kernel<<<MR_, 256>>>(tmpp, ln1g, ln1b, x1p, x1rp);

    // FFN (EpiGelu rounds ff for W2 GEMM; residual uses exact x1)
    gemm_tf32<<<dim3(FF_/128, MR_/128), blk, GEMM_SMEM>>>(x1rp, w1r, MR_, FF_, H_, EpiGelu{b1, ffp});
    gemm_tf32<<<dim3(H_/128, MR_/128), blk, GEMM_SMEM>>>(ffp, w2r, MR_, H_, FF_, EpiBiasRes{b2, x1p, tmpp});
    ln_kernel<<<MR_, 256>>>(tmpp, ln2g, ln2b, out, nullptr);
}